// round 16
// baseline (speedup 1.0000x reference)
#include <cuda_runtime.h>

// CTC forward scan split at T/2 (fwd + mirrored bwd halves on separate CTAs),
// combine = -LSE_m(F[m]+B[m]) * ln2 / T (separate small kernel).
// TWO-STEP FUSION: f''[p] = lae3(S2+f[p], M1[sj(p)]+f[p-1], M2[sj(p-1),sj(p)]+f[p-2]).
// NEW vs R11: 512 threads = 16 warps (4/SMSP), lane owns ONE position.
// 4 independent recurrence chains per SMSP hide the shfl+lae3 chain latency.
// K_EPOCH=16 (8 fused iters/epoch) keeps 16-warp skew fill low; coef ring has
// 17 slabs (skew 16 + writer). Exact 2-MUFU lae3 everywhere.

#define T_STEPS   4096
#define T_HALF    2048
#define BATCH     64
#define NFEAT     5
#define P_POS     512
#define NEG_LARGE (-1e30f)
#define K_EPOCH   16
#define NITER     8                       // fused iterations per chunk
#define NCHUNK    (T_HALF / K_EPOCH)      // 128
#define NTHREADS  512
#define NWARPS    16
#define NEPOCH    (NCHUNK + NWARPS - 1)   // 143
#define GSTRIDE   24                      // S2, M1[4], M2[16], pad
#define CSTRIDE   (NITER * GSTRIDE)       // 192 floats per chunk slab
#define NCSLAB    17                      // >= skew(16) + writer(1)
#define L2E       1.4426950408889634f
#define LN2F      0.6931471805599453f

__device__ float g_scrF[BATCH * (P_POS + 1)];
__device__ float g_scrB[BATCH * (P_POS + 1)];

__device__ __forceinline__ float ex2f(float v){ float r; asm("ex2.approx.f32 %0,%1;" : "=f"(r) : "f"(v)); return r; }
__device__ __forceinline__ float lg2f(float v){ float r; asm("lg2.approx.f32 %0,%1;" : "=f"(r) : "f"(v)); return r; }

// accurate 2-MUFU logaddexp (log2 domain) — staging only
__device__ __forceinline__ float lae2(float a, float b) {
    float m = fmaxf(a, b);
    float d = -fabsf(a - b);
    return m + lg2f(1.0f + ex2f(d));
}

// 3-way logaddexp (log2 domain): max term's ex2 (==1) skipped via sort. Exact MUFU.
__device__ __forceinline__ float lae3(float a, float b, float c) {
    float u1 = fminf(a, b);
    float u2 = fmaxf(a, b);
    float m  = fmaxf(u2, c);
    float v  = fminf(u2, c);
    float y  = 1.0f + (ex2f(u1 - m) + ex2f(v - m));
    return m + lg2f(y);
}

__global__ void __launch_bounds__(NTHREADS, 1)
ctc_half_kernel(const float* __restrict__ x,
                const int*   __restrict__ seqs,
                const int*   __restrict__ seqlens)
{
    const bool fwdDir = (blockIdx.x & 1) == 0;
    const int  b      = blockIdx.x >> 1;
    const int  tid    = threadIdx.x;
    const int  lane   = tid & 31;
    const int  w      = tid >> 5;

    __shared__ float  cof[NCSLAB * CSTRIDE];   // fused coefs (ring, 17 slabs)
    __shared__ float2 bnd[2][NWARPS][NITER];   // (f[32w-1], f[32w]) entering iter k

    const float* xb = x + b * NFEAT;           // x[t*B*F + b*F + f]
    const int    TB = BATCH * NFEAT;

    // ---- coef staging: 8 groups (step-pairs) x 64 threads; entry j < 21 ----
    // j==0: S2 | j in 1..4: M1[j-1] (lae2) | j in 5..20: M2[j-5] (add)
    const int g  = tid >> 6;                   // group 0..7
    const int j  = tid & 63;
    const bool act = (j < 21);
    const bool isM1 = (j >= 1 && j <= 4);
    int fa0 = 4, fa1 = 4;
    if (isM1)            { fa0 = j - 1; fa1 = j - 1; }
    else if (j >= 5 && act) { int ei = j - 5; fa0 = ei >> 2; fa1 = ei & 3; }

    // ---- per-lane recurrence setup: lane owns position p = pb+1, pb = 32w+lane ----
    const int pb = (w << 5) + lane;
    const int* sp = seqs + b * P_POS;
    int si0, idxA;                             // sj(p), sj(p-1)
    if (fwdDir) {
        si0  = sp[pb];
        idxA = (pb >= 1) ? sp[pb - 1] : 0;
    } else {
        si0  = sp[P_POS - 1 - pb];
        idxA = (pb >= 1) ? sp[P_POS - pb] : 0;
    }
    const int m1o = 1 + si0;
    const int m2o = 5 + idxA * 4 + si0;

    const int q0 = P_POS - seqlens[b];
    float f, fz;
    if (fwdDir) {
        f = NEG_LARGE; fz = 0.0f;
    } else {
        f  = (pb + 1 == q0) ? 0.f : NEG_LARGE;
        fz = (q0 == 0) ? 0.f : NEG_LARGE;
    }

    for (int i = tid; i < 2 * NWARPS * NITER; i += NTHREADS)
        (&bnd[0][0][0])[i] = make_float2(NEG_LARGE, NEG_LARGE);

    #define GTIME(s) (fwdDir ? (s) : (T_STEPS - 1 - (s)))

    // ---- prologue: stage coefs for chunk 0 into slab 0 ----
    if (act) {
        const int s0 = 2 * g, s1 = s0 + 1;
        const long o0 = (long)GTIME(s0) * TB, o1 = (long)GTIME(s1) * TB;
        float a0 = xb[o0 + fa0] * L2E;
        float a1 = xb[o1 + fa1] * L2E;
        float st0 = 0.f, st1 = 0.f;
        if (isM1) { st0 = xb[o0 + 4] * L2E; st1 = xb[o1 + 4] * L2E; }
        cof[g * GSTRIDE + j] = isM1 ? lae2(a0 + st1, st0 + a1) : (a0 + a1);
    }
    __syncthreads();

    for (int e = 0; e < NEPOCH; ++e) {
        // ---- issue LDGs for chunk e+1 coef inputs (hidden under compute) ----
        float a0 = 0.f, a1 = 0.f, st0 = 0.f, st1 = 0.f;
        const bool pf = (e + 1) < NCHUNK;
        if (pf && act) {
            const int s0 = (e + 1) * K_EPOCH + 2 * g, s1 = s0 + 1;
            const long o0 = (long)GTIME(s0) * TB, o1 = (long)GTIME(s1) * TB;
            a0 = xb[o0 + fa0] * L2E;
            a1 = xb[o1 + fa1] * L2E;
            if (isM1) { st0 = xb[o0 + 4] * L2E; st1 = xb[o1 + 4] * L2E; }
        }

        const int  c     = e - w;
        const bool valid = (c >= 0) && (c < NCHUNK);

        if (valid) {
            const float*  cs = cof + (c % NCSLAB) * CSTRIDE;
            const float2* bR = bnd[(e & 1) ^ 1][(w > 0) ? (w - 1) : 0];
            float2*       bW = &bnd[e & 1][w][0];

            #pragma unroll
            for (int k = 0; k < NITER; ++k) {
                const float* gb = cs + k * GSTRIDE;
                float S2 = gb[0];
                float M1 = gb[m1o];
                float M2 = gb[m2o];
                float2 bv = bR[k];

                float Lf1 = __shfl_up_sync(0xffffffffu, f, 1);   // f[p-1]
                float Lf2 = __shfl_up_sync(0xffffffffu, f, 2);   // f[p-2]
                if (lane == 31) bW[k] = make_float2(Lf1, f);     // (f[32w-1], f[32w]) entering k
                if (lane == 0) {
                    Lf1 = w ? bv.y : fz;
                    Lf2 = w ? bv.x : NEG_LARGE;
                } else if (lane == 1) {
                    Lf2 = w ? bv.y : fz;
                }

                float A = S2 + f;
                float B = M1 + Lf1;
                float C = M2 + Lf2;
                if (w == 0) fz += S2;

                f = lae3(A, B, C);
            }
        }

        // ---- compute + commit coefs for chunk e+1 ----
        if (pf && act) {
            float* gb = cof + ((e + 1) % NCSLAB) * CSTRIDE + g * GSTRIDE;
            gb[j] = isM1 ? lae2(a0 + st1, st0 + a1) : (a0 + a1);
        }
        __syncthreads();
    }

    // ---- epilogue: write half-result. fwd: index = position; bwd: m = P - q. ----
    float* scr = fwdDir ? (g_scrF + b * (P_POS + 1)) : (g_scrB + b * (P_POS + 1));
    if (fwdDir) {
        scr[pb + 1] = f;
        if (tid == 0) scr[0] = fz;
    } else {
        scr[P_POS - (pb + 1)] = f;
        if (tid == 0) scr[P_POS] = fz;
    }
}

__global__ void __launch_bounds__(128)
ctc_combine_kernel(float* __restrict__ out)
{
    const int b    = blockIdx.x;
    const int tid  = threadIdx.x;
    const int lane = tid & 31;
    const int w    = tid >> 5;
    __shared__ float red[4];

    const float* F = g_scrF + b * (P_POS + 1);
    const float* B = g_scrB + b * (P_POS + 1);

    float vm = -3e38f;
    float v[5];
    int   nv = 0;
    for (int p = tid; p <= P_POS; p += 128) {
        float t = F[p] + B[p];
        v[nv++] = t;
        vm = fmaxf(vm, t);
    }
    #pragma unroll
    for (int off = 16; off; off >>= 1)
        vm = fmaxf(vm, __shfl_xor_sync(0xffffffffu, vm, off));
    if (lane == 0) red[w] = vm;
    __syncthreads();
    vm = fmaxf(fmaxf(red[0], red[1]), fmaxf(red[2], red[3]));

    float s = 0.f;
    for (int i = 0; i < nv; ++i) s += ex2f(v[i] - vm);
    #pragma unroll
    for (int off = 16; off; off >>= 1)
        s += __shfl_xor_sync(0xffffffffu, s, off);
    __syncthreads();
    if (lane == 0) red[w] = s;
    __syncthreads();
    if (tid == 0) {
        float st = red[0] + red[1] + red[2] + red[3];
        float lse = vm + lg2f(st);
        out[b] = -lse * (LN2F / (float)T_STEPS);
    }
}

extern "C" void kernel_launch(void* const* d_in, const int* in_sizes, int n_in,
                              void* d_out, int out_size)
{
    const float* x       = (const float*)d_in[0];
    const int*   seqs    = (const int*)  d_in[1];
    const int*   seqlens = (const int*)  d_in[2];
    float*       out     = (float*)      d_out;

    ctc_half_kernel<<<2 * BATCH, NTHREADS>>>(x, seqs, seqlens);
    ctc_combine_kernel<<<BATCH, 128>>>(out);
}

// round 17
// speedup vs baseline: 1.9427x; 1.9427x over previous
#include <cuda_runtime.h>

// CTC forward scan split at T/2 (fwd + mirrored bwd halves on separate CTAs),
// combine = -LSE_m(F[m]+B[m]) * ln2 / T.
// TWO-STEP FUSION: f''[p] = lae3(S2+f[p], M1[sj(p)]+f[p-1], M2[sj(p-1),sj(p)]+f[p-2]).
// R11 core (8 warps, lane owns 2 positions, exact 2-MUFU lae3, one barrier/epoch),
// with K_EPOCH=16: NITER=8, NCHUNK=128, NEPOCH=135 -> wavefront fill overhead
// drops 11% -> 5.5%. Coefs (S2,M1[4],M2[16]) staged by 8 groups x 32 threads
// (entry j<21, one entry per thread) from gmem registers into a 16-slab ring.

#define T_STEPS   4096
#define T_HALF    2048
#define BATCH     64
#define NFEAT     5
#define P_POS     512
#define NEG_LARGE (-1e30f)
#define K_EPOCH   16
#define NITER     8                       // fused iterations per chunk
#define NCHUNK    (T_HALF / K_EPOCH)      // 128
#define NTHREADS  256
#define NWARPS    8
#define NEPOCH    (NCHUNK + NWARPS - 1)   // 135
#define GSTRIDE   24                      // S2, M1[4], M2[16], pad
#define CSTRIDE   (NITER * GSTRIDE)       // 192 floats per chunk slab
#define NCSLAB    16                      // power of 2; skew(7)+writer(1) < 16
#define L2E       1.4426950408889634f
#define LN2F      0.6931471805599453f

__device__ float g_scrF[BATCH * (P_POS + 1)];
__device__ float g_scrB[BATCH * (P_POS + 1)];

__device__ __forceinline__ float ex2f(float v){ float r; asm("ex2.approx.f32 %0,%1;" : "=f"(r) : "f"(v)); return r; }
__device__ __forceinline__ float lg2f(float v){ float r; asm("lg2.approx.f32 %0,%1;" : "=f"(r) : "f"(v)); return r; }

// accurate 2-MUFU logaddexp (log2 domain) — staging only
__device__ __forceinline__ float lae2(float a, float b) {
    float m = fmaxf(a, b);
    float d = -fabsf(a - b);
    return m + lg2f(1.0f + ex2f(d));
}

// 3-way logaddexp (log2 domain): max term's ex2 (==1) skipped via sort. Exact MUFU.
__device__ __forceinline__ float lae3(float a, float b, float c) {
    float u1 = fminf(a, b);
    float u2 = fmaxf(a, b);
    float m  = fmaxf(u2, c);
    float v  = fminf(u2, c);
    float y  = 1.0f + (ex2f(u1 - m) + ex2f(v - m));
    return m + lg2f(y);
}

__global__ void __launch_bounds__(NTHREADS, 1)
ctc_half_kernel(const float* __restrict__ x,
                const int*   __restrict__ seqs,
                const int*   __restrict__ seqlens)
{
    const bool fwdDir = (blockIdx.x & 1) == 0;
    const int  b      = blockIdx.x >> 1;
    const int  tid    = threadIdx.x;
    const int  lane   = tid & 31;
    const int  w      = tid >> 5;

    __shared__ float  cof[NCSLAB * CSTRIDE];   // fused coefs per chunk (ring)
    __shared__ float2 bnd[2][NWARPS][NITER];   // lane31 (f0,f1) entering iter k

    const float* xb = x + b * NFEAT;           // x[t*B*F + b*F + f]
    const int    TB = BATCH * NFEAT;

    // ---- coef staging: 8 groups (step-pairs) x 32 threads; entry j < 21 ----
    // j==0: S2 | j in 1..4: M1[j-1] (lae2) | j in 5..20: M2[j-5] (add)
    const int g   = tid >> 5;                  // group 0..7 (== warp id)
    const int j   = tid & 31;
    const bool act  = (j < 21);
    const bool isM1 = (j >= 1 && j <= 4);
    int fa0 = 4, fa1 = 4;
    if (isM1)               { fa0 = j - 1; fa1 = j - 1; }
    else if (act && j >= 5) { int ei = j - 5; fa0 = ei >> 2; fa1 = ei & 3; }

    // ---- per-lane recurrence setup: lane owns positions pb+1, pb+2 ----
    const int pb = (w << 6) + (lane << 1);
    const int* sp = seqs + b * P_POS;
    int si0, si1, idxA;                        // sj(p0), sj(p1), sj(p0-1)
    if (fwdDir) {
        si0  = sp[pb];
        si1  = sp[pb + 1];
        idxA = (pb == 0) ? 0 : sp[pb - 1];
    } else {
        si0  = sp[P_POS - 1 - pb];
        si1  = sp[P_POS - 2 - pb];
        idxA = (pb == 0) ? 0 : sp[P_POS - pb];
    }
    const int m1o0 = 1 + si0;
    const int m1o1 = 1 + si1;
    const int m2o0 = 5 + idxA * 4 + si0;
    const int m2o1 = 5 + si0  * 4 + si1;

    const int q0 = P_POS - seqlens[b];
    float f0, f1, fz;
    if (fwdDir) {
        f0 = f1 = NEG_LARGE; fz = 0.0f;
    } else {
        f0 = (pb + 1 == q0) ? 0.f : NEG_LARGE;
        f1 = (pb + 2 == q0) ? 0.f : NEG_LARGE;
        fz = (q0 == 0) ? 0.f : NEG_LARGE;
    }

    for (int i = tid; i < 2 * NWARPS * NITER; i += NTHREADS)
        (&bnd[0][0][0])[i] = make_float2(NEG_LARGE, NEG_LARGE);

    #define GTIME(s) (fwdDir ? (s) : (T_STEPS - 1 - (s)))

    // ---- prologue: stage coefs for chunk 0 into slab 0 ----
    if (act) {
        const int s0 = 2 * g, s1 = s0 + 1;
        const long o0 = (long)GTIME(s0) * TB, o1 = (long)GTIME(s1) * TB;
        float a0 = xb[o0 + fa0] * L2E;
        float a1 = xb[o1 + fa1] * L2E;
        float st0 = 0.f, st1 = 0.f;
        if (isM1) { st0 = xb[o0 + 4] * L2E; st1 = xb[o1 + 4] * L2E; }
        cof[g * GSTRIDE + j] = isM1 ? lae2(a0 + st1, st0 + a1) : (a0 + a1);
    }
    __syncthreads();

    for (int e = 0; e < NEPOCH; ++e) {
        // ---- issue LDGs for chunk e+1 coef inputs (hidden under compute) ----
        float a0 = 0.f, a1 = 0.f, st0 = 0.f, st1 = 0.f;
        const bool pf = (e + 1) < NCHUNK;
        if (pf && act) {
            const int s0 = (e + 1) * K_EPOCH + 2 * g, s1 = s0 + 1;
            const long o0 = (long)GTIME(s0) * TB, o1 = (long)GTIME(s1) * TB;
            a0 = xb[o0 + fa0] * L2E;
            a1 = xb[o1 + fa1] * L2E;
            if (isM1) { st0 = xb[o0 + 4] * L2E; st1 = xb[o1 + 4] * L2E; }
        }

        const int  c     = e - w;
        const bool valid = (c >= 0) && (c < NCHUNK);

        if (valid) {
            const float*  cs = cof + (c & (NCSLAB - 1)) * CSTRIDE;
            const float2* bR = bnd[(e & 1) ^ 1][(w > 0) ? (w - 1) : 0];
            float2*       bW = &bnd[e & 1][w][0];

            #pragma unroll
            for (int k = 0; k < NITER; ++k) {
                const float* gb  = cs + k * GSTRIDE;
                float S2  = gb[0];
                float M1a = gb[m1o0];
                float M1b = gb[m1o1];
                float M2a = gb[m2o0];
                float M2b = gb[m2o1];
                float2 bv = bR[k];

                float Lf0 = __shfl_up_sync(0xffffffffu, f0, 1);
                float Lf1 = __shfl_up_sync(0xffffffffu, f1, 1);
                if (lane == 0) {
                    Lf0 = (w == 0) ? NEG_LARGE : bv.x;
                    Lf1 = (w == 0) ? fz        : bv.y;
                }
                if (lane == 31) bW[k] = make_float2(f0, f1);

                float A0 = S2 + f0;
                float B0 = M1a + Lf1;
                float C0 = M2a + Lf0;
                float A1 = S2 + f1;
                float B1 = M1b + f0;     // old f0
                float C1 = M2b + Lf1;
                if (w == 0) fz += S2;

                f0 = lae3(A0, B0, C0);
                f1 = lae3(A1, B1, C1);
            }
        }

        // ---- compute + commit coefs for chunk e+1 ----
        if (pf && act) {
            float* gb = cof + ((e + 1) & (NCSLAB - 1)) * CSTRIDE + g * GSTRIDE;
            gb[j] = isM1 ? lae2(a0 + st1, st0 + a1) : (a0 + a1);
        }
        __syncthreads();
    }

    // ---- epilogue: write half-result. fwd: index = position; bwd: m = P - q. ----
    float* scr = fwdDir ? (g_scrF + b * (P_POS + 1)) : (g_scrB + b * (P_POS + 1));
    if (fwdDir) {
        scr[pb + 1] = f0; scr[pb + 2] = f1;
        if (tid == 0) scr[0] = fz;
    } else {
        scr[P_POS - (pb + 1)] = f0;
        scr[P_POS - (pb + 2)] = f1;
        if (tid == 0) scr[P_POS] = fz;
    }
}

__global__ void __launch_bounds__(128)
ctc_combine_kernel(float* __restrict__ out)
{
    const int b    = blockIdx.x;
    const int tid  = threadIdx.x;
    const int lane = tid & 31;
    const int w    = tid >> 5;
    __shared__ float red[4];

    const float* F = g_scrF + b * (P_POS + 1);
    const float* B = g_scrB + b * (P_POS + 1);

    float vm = -3e38f;
    float v[5];
    int   nv = 0;
    for (int p = tid; p <= P_POS; p += 128) {
        float t = F[p] + B[p];
        v[nv++] = t;
        vm = fmaxf(vm, t);
    }
    #pragma unroll
    for (int off = 16; off; off >>= 1)
        vm = fmaxf(vm, __shfl_xor_sync(0xffffffffu, vm, off));
    if (lane == 0) red[w] = vm;
    __syncthreads();
    vm = fmaxf(fmaxf(red[0], red[1]), fmaxf(red[2], red[3]));

    float s = 0.f;
    for (int i = 0; i < nv; ++i) s += ex2f(v[i] - vm);
    #pragma unroll
    for (int off = 16; off; off >>= 1)
        s += __shfl_xor_sync(0xffffffffu, s, off);
    __syncthreads();
    if (lane == 0) red[w] = s;
    __syncthreads();
    if (tid == 0) {
        float st = red[0] + red[1] + red[2] + red[3];
        float lse = vm + lg2f(st);
        out[b] = -lse * (LN2F / (float)T_STEPS);
    }
}

extern "C" void kernel_launch(void* const* d_in, const int* in_sizes, int n_in,
                              void* d_out, int out_size)
{
    const float* x       = (const float*)d_in[0];
    const int*   seqs    = (const int*)  d_in[1];
    const int*   seqlens = (const int*)  d_in[2];
    float*       out     = (float*)      d_out;

    ctc_half_kernel<<<2 * BATCH, NTHREADS>>>(x, seqs, seqlens);
    ctc_combine_kernel<<<BATCH, 128>>>(out);
}